// round 8
// baseline (speedup 1.0000x reference)
#include <cuda_runtime.h>
#include <cstddef>

#define DD      512
#define HWV     1024
#define NTOK    16384
#define NBLK    296            // 148 SMs x 2 CTAs -> one wave
#define TPB     512
#define TOKTILE 8
#define NTILES  2048           // NTOK / TOKTILE
#define TILEF   (TOKTILE * DD) // floats per smem buffer (4096 = 16KB)

#define SC32  4294967296.0     // 2^32 fixed-point scale (per-d stats)
#define IS32  (1.0 / 4294967296.0)
#define SC30  1073741824.0     // 2^30 fixed-point scale (bracket)
#define IS30  (1.0 / 1073741824.0)

// scratch (device globals zero-initialized; self-reset after use -> replayable)
__device__ unsigned long long g_accI[DD][4];  // {sinv, smui, s1, s2} fixed-point
__device__ unsigned long long g_brI;          // bracket fixed-point
__device__ unsigned           g_cnt;          // completion counter

// ---------------------------------------------------------------------------
// Single fused kernel. Mainloop identical to R6/R7 pass1:
// double-buffered smem x-transpose, one sync per tile, pipeline order
// [mu/lv LDG] [next-x LDG] [compute] [next-x STS] [sync].
// Epilogue: deterministic i64 fixed-point atomics + last-block final sum.
// ---------------------------------------------------------------------------
__global__ __launch_bounds__(TPB, 2)
void club_fused(const float* __restrict__ x,
                const float* __restrict__ mu,
                const float* __restrict__ lv,
                float* __restrict__ out)
{
    __shared__ float sx[2 * TILEF];        // 32 KB
    const int tid = threadIdx.x;
    const int blk = blockIdx.x;
    const int dg  = tid & 127;
    const int sub = tid >> 7;

    const int gA = tid >> 2;               // d-group for STS (d = tid)
    const int kA = tid & 3;

    float a_sinv[4] = {0,0,0,0};
    float a_smui[4] = {0,0,0,0};
    float a_s1[4]   = {0,0,0,0};
    float a_s2[4]   = {0,0,0,0};
    float a_br = 0.f;

    // ---- prologue: stage tile 'blk' into buffer 0 ----
    {
        const float* xr = x + (size_t)(blk >> 7) * DD * HWV
                            + (size_t)tid * HWV + (blk & 127) * TOKTILE;
        const float4 xa0 = *reinterpret_cast<const float4*>(xr);
        const float4 xa1 = *reinterpret_cast<const float4*>(xr + 4);
        sx[0*DD + 4*(gA ^ 0) + kA] = xa0.x;
        sx[1*DD + 4*(gA ^ 0) + kA] = xa0.y;
        sx[2*DD + 4*(gA ^ 1) + kA] = xa0.z;
        sx[3*DD + 4*(gA ^ 1) + kA] = xa0.w;
        sx[4*DD + 4*(gA ^ 2) + kA] = xa1.x;
        sx[5*DD + 4*(gA ^ 2) + kA] = xa1.y;
        sx[6*DD + 4*(gA ^ 3) + kA] = xa1.z;
        sx[7*DD + 4*(gA ^ 3) + kA] = xa1.w;
    }
    __syncthreads();

    int p = 0;
    for (int t = blk; t < NTILES; t += NBLK) {
        const int nxt = t + NBLK;
        const int t0  = t * TOKTILE;

        // ---- issue mu/lv loads (consumed first in compute) ----
        const float* mup = mu + (size_t)(t0 + sub * 2) * DD + 4 * dg;
        const float* lvp = lv + (size_t)(t0 + sub * 2) * DD + 4 * dg;
        const float4 m0 = *reinterpret_cast<const float4*>(mup);
        const float4 m1 = *reinterpret_cast<const float4*>(mup + DD);
        const float4 l0 = *reinterpret_cast<const float4*>(lvp);
        const float4 l1 = *reinterpret_cast<const float4*>(lvp + DD);

        // ---- issue next-tile x loads (latency hidden under compute) ----
        float4 xn0, xn1;
        if (nxt < NTILES) {
            const float* xr = x + (size_t)(nxt >> 7) * DD * HWV
                                + (size_t)tid * HWV + (nxt & 127) * TOKTILE;
            xn0 = *reinterpret_cast<const float4*>(xr);
            xn1 = *reinterpret_cast<const float4*>(xr + 4);
        }

        // ---- compute on current buffer ----
        {
            const float* cb = sx + p * TILEF;
            #pragma unroll
            for (int j = 0; j < 2; j++) {
                const int ts = sub * 2 + j;
                const float4 xv = *reinterpret_cast<const float4*>(
                    &cb[ts * DD + 4 * (dg ^ ((ts >> 1) & 7))]);
                const float4 mm4 = (j == 0) ? m0 : m1;
                const float4 ll4 = (j == 0) ? l0 : l1;
                float mm[4] = {mm4.x, mm4.y, mm4.z, mm4.w};
                float ll[4] = {ll4.x, ll4.y, ll4.z, ll4.w};
                float xx[4] = {xv.x, xv.y, xv.z, xv.w};
                #pragma unroll
                for (int k = 0; k < 4; k++) {
                    float iv = __expf(-ll[k]);
                    a_sinv[k] += iv;
                    a_smui[k] += mm[k] * iv;
                    a_s1[k]   += xx[k];
                    a_s2[k]   += xx[k] * xx[k];
                    a_br      += (xx[k] - 2.0f * mm[k]) * xx[k] * iv;
                }
            }
        }

        // ---- stage next tile into the other buffer ----
        if (nxt < NTILES) {
            float* sb = sx + (p ^ 1) * TILEF;
            sb[0*DD + 4*(gA ^ 0) + kA] = xn0.x;
            sb[1*DD + 4*(gA ^ 0) + kA] = xn0.y;
            sb[2*DD + 4*(gA ^ 1) + kA] = xn0.z;
            sb[3*DD + 4*(gA ^ 1) + kA] = xn0.w;
            sb[4*DD + 4*(gA ^ 2) + kA] = xn1.x;
            sb[5*DD + 4*(gA ^ 2) + kA] = xn1.y;
            sb[6*DD + 4*(gA ^ 3) + kA] = xn1.z;
            sb[7*DD + 4*(gA ^ 3) + kA] = xn1.w;
        }
        __syncthreads();
        p ^= 1;
    }

    // ---- cross-sub combine via SMEM -> per-d float4 (d = tid) ----
    #pragma unroll
    for (int k = 0; k < 4; k++) {
        int base = (sub * 128 + dg) * 16 + k * 4;
        sx[base + 0] = a_sinv[k];
        sx[base + 1] = a_smui[k];
        sx[base + 2] = a_s1[k];
        sx[base + 3] = a_s2[k];
    }
    __syncthreads();
    {
        const int d   = tid;
        const int dg2 = d >> 2, kk = d & 3;
        float4 acc = make_float4(0.f, 0.f, 0.f, 0.f);
        #pragma unroll
        for (int sb = 0; sb < 4; sb++) {
            int base = (sb * 128 + dg2) * 16 + kk * 4;
            acc.x += sx[base + 0];
            acc.y += sx[base + 1];
            acc.z += sx[base + 2];
            acc.w += sx[base + 3];
        }
        // deterministic i64 fixed-point accumulation (integer add = associative)
        atomicAdd(&g_accI[d][0], (unsigned long long)llrint((double)acc.x * SC32));
        atomicAdd(&g_accI[d][1], (unsigned long long)llrint((double)acc.y * SC32));
        atomicAdd(&g_accI[d][2], (unsigned long long)llrint((double)acc.z * SC32));
        atomicAdd(&g_accI[d][3], (unsigned long long)llrint((double)acc.w * SC32));
    }
    __syncthreads();

    // ---- block tree-reduce bracket, one i64 atomic per block ----
    sx[tid] = a_br;
    __syncthreads();
    #pragma unroll
    for (int off = 256; off > 0; off >>= 1) {
        if (tid < off) sx[tid] += sx[tid + off];
        __syncthreads();
    }
    if (tid == 0)
        atomicAdd(&g_brI, (unsigned long long)llrint((double)sx[0] * SC30));

    // ---- publish, then count completed blocks ----
    __threadfence();
    __shared__ unsigned rank_;
    if (tid == 0) rank_ = atomicAdd(&g_cnt, 1u);
    __syncthreads();

    if (rank_ == NBLK - 1) {
        __threadfence();
        __shared__ double sd[TPB];
        long long i0 = (long long)__ldcg(&g_accI[tid][0]);
        long long i1 = (long long)__ldcg(&g_accI[tid][1]);
        long long i2 = (long long)__ldcg(&g_accI[tid][2]);
        long long i3 = (long long)__ldcg(&g_accI[tid][3]);
        double sinv = (double)i0 * IS32;
        double smui = (double)i1 * IS32;
        double m1   = (double)i2 * IS32 / (double)NTOK;
        double m2   = (double)i3 * IS32 / (double)NTOK;
        double c = -(m2 * sinv) + 2.0 * m1 * smui;
        if (tid == 0)
            c += (double)(long long)__ldcg(&g_brI) * IS30;
        sd[tid] = c;
        __syncthreads();
        #pragma unroll
        for (int off = 256; off > 0; off >>= 1) {
            if (tid < off) sd[tid] += sd[tid + off];
            __syncthreads();
        }
        if (tid == 0)
            out[0] = (float)(-0.5 / (double)NTOK * sd[0]);

        // self-reset for next graph replay (safe: all blocks have arrived)
        g_accI[tid][0] = 0ull;
        g_accI[tid][1] = 0ull;
        g_accI[tid][2] = 0ull;
        g_accI[tid][3] = 0ull;
        if (tid == 0) { g_brI = 0ull; g_cnt = 0u; }
    }
}

// ---------------------------------------------------------------------------
extern "C" void kernel_launch(void* const* d_in, const int* in_sizes, int n_in,
                              void* d_out, int out_size)
{
    (void)in_sizes; (void)n_in; (void)out_size;
    const float* x  = (const float*)d_in[0];
    const float* mu = (const float*)d_in[1];
    const float* lv = (const float*)d_in[2];
    float* out = (float*)d_out;

    club_fused<<<NBLK, TPB>>>(x, mu, lv, out);
}

// round 9
// speedup vs baseline: 1.0938x; 1.0938x over previous
#include <cuda_runtime.h>
#include <cstddef>
#include <cstdint>

#define DD      512
#define HWV     1024
#define NTOK    16384
#define NBLK    296            // 148 SMs x 2 CTAs -> one wave
#define NBP     320            // padded block rows (rows >=296 stay 0)
#define TPB     512
#define TOKTILE 8
#define NTILES  2048           // NTOK / TOKTILE
#define TILEF   (TOKTILE * DD) // floats per tile buffer (4096 = 16KB)

// scratch (device globals zero-initialized; no allocation allowed)
// [d * NBP + blk] -> pass2 warp reads coalesced
__device__ float4 g_part4[DD * NBP];
__device__ float  g_br[NBLK];
__device__ double g_cd[DD];

__device__ __forceinline__ void cpa16(uint32_t s, const void* g) {
    asm volatile("cp.async.cg.shared.global [%0], [%1], 16;" :: "r"(s), "l"(g));
}

// ---------------------------------------------------------------------------
// Pass 1: single sweep. Software pipeline depth 2 on EVERYTHING:
//   x: LDG.128 -> swizzled scalar STS (transpose), double-buffered
//   mu/lv: cp.async (register-free) into SMEM, double-buffered
// Per iteration: [wait_group 0][sync][cp.async next mu/lv][LDG next x]
//                [compute from smem][STS next x]
// Thread t -> dg = t&127 (d = 4dg..4dg+3), sub = t>>7 (2-token subset).
// ---------------------------------------------------------------------------
__global__ __launch_bounds__(TPB, 2)
void club_pass1(const float* __restrict__ x,
                const float* __restrict__ mu,
                const float* __restrict__ lv)
{
    extern __shared__ float smemf[];
    float* sxx = smemf;                 // x  buffers [2][TILEF] (swizzled)
    float* smu = smemf + 2 * TILEF;     // mu buffers [2][TILEF]
    float* slv = smemf + 4 * TILEF;     // lv buffers [2][TILEF]
    const uint32_t smu32 = (uint32_t)__cvta_generic_to_shared(smu);
    const uint32_t slv32 = (uint32_t)__cvta_generic_to_shared(slv);

    const int tid = threadIdx.x;
    const int blk = blockIdx.x;
    const int dg  = tid & 127;
    const int sub = tid >> 7;
    const int gA  = tid >> 2;           // d-group for x STS (d = tid)
    const int kA  = tid & 3;

    float a_sinv[4] = {0,0,0,0};
    float a_smui[4] = {0,0,0,0};
    float a_s1[4]   = {0,0,0,0};
    float a_s2[4]   = {0,0,0,0};
    float a_br = 0.f;

    // ---- prologue: cp.async mu/lv(tile blk) -> buf0 ; x(tile blk) -> buf0 ----
    {
        const float* ms = mu + (size_t)blk * TILEF;
        const float* ls = lv + (size_t)blk * TILEF;
        cpa16(smu32 + tid * 16,         ms + tid * 4);
        cpa16(smu32 + (tid + TPB) * 16, ms + (tid + TPB) * 4);
        cpa16(slv32 + tid * 16,         ls + tid * 4);
        cpa16(slv32 + (tid + TPB) * 16, ls + (tid + TPB) * 4);
        asm volatile("cp.async.commit_group;");

        const float* xr = x + (size_t)(blk >> 7) * DD * HWV
                            + (size_t)tid * HWV + (blk & 127) * TOKTILE;
        const float4 xa0 = *reinterpret_cast<const float4*>(xr);
        const float4 xa1 = *reinterpret_cast<const float4*>(xr + 4);
        sxx[0*DD + 4*(gA ^ 0) + kA] = xa0.x;
        sxx[1*DD + 4*(gA ^ 0) + kA] = xa0.y;
        sxx[2*DD + 4*(gA ^ 1) + kA] = xa0.z;
        sxx[3*DD + 4*(gA ^ 1) + kA] = xa0.w;
        sxx[4*DD + 4*(gA ^ 2) + kA] = xa1.x;
        sxx[5*DD + 4*(gA ^ 2) + kA] = xa1.y;
        sxx[6*DD + 4*(gA ^ 3) + kA] = xa1.z;
        sxx[7*DD + 4*(gA ^ 3) + kA] = xa1.w;
    }

    int p = 0;
    for (int t = blk; t < NTILES; t += NBLK) {
        const int nxt = t + NBLK;

        // ---- current tile's mu/lv complete; also closes prior compute ----
        asm volatile("cp.async.wait_group 0;");
        __syncthreads();

        // ---- issue next tile's mu/lv (runs during compute) ----
        if (nxt < NTILES) {
            const float* ms = mu + (size_t)nxt * TILEF;
            const float* ls = lv + (size_t)nxt * TILEF;
            const uint32_t mb = smu32 + (p ^ 1) * TILEF * 4;
            const uint32_t lb = slv32 + (p ^ 1) * TILEF * 4;
            cpa16(mb + tid * 16,         ms + tid * 4);
            cpa16(mb + (tid + TPB) * 16, ms + (tid + TPB) * 4);
            cpa16(lb + tid * 16,         ls + tid * 4);
            cpa16(lb + (tid + TPB) * 16, ls + (tid + TPB) * 4);
            asm volatile("cp.async.commit_group;");
        }

        // ---- issue next tile's x loads ----
        float4 xn0, xn1;
        if (nxt < NTILES) {
            const float* xr = x + (size_t)(nxt >> 7) * DD * HWV
                                + (size_t)tid * HWV + (nxt & 127) * TOKTILE;
            xn0 = *reinterpret_cast<const float4*>(xr);
            xn1 = *reinterpret_cast<const float4*>(xr + 4);
        }

        // ---- compute from current buffers ----
        {
            const float* cbx = sxx + p * TILEF;
            const float* cbm = smu + p * TILEF;
            const float* cbl = slv + p * TILEF;
            #pragma unroll
            for (int j = 0; j < 2; j++) {
                const int ts  = sub * 2 + j;
                const int idx = ts * DD + 4 * dg;
                const float4 mm4 = *reinterpret_cast<const float4*>(cbm + idx);
                const float4 ll4 = *reinterpret_cast<const float4*>(cbl + idx);
                const float4 xv  = *reinterpret_cast<const float4*>(
                    cbx + ts * DD + 4 * (dg ^ ((ts >> 1) & 7)));
                float mm[4] = {mm4.x, mm4.y, mm4.z, mm4.w};
                float ll[4] = {ll4.x, ll4.y, ll4.z, ll4.w};
                float xx[4] = {xv.x, xv.y, xv.z, xv.w};
                #pragma unroll
                for (int k = 0; k < 4; k++) {
                    float iv = __expf(-ll[k]);
                    a_sinv[k] += iv;
                    a_smui[k] += mm[k] * iv;
                    a_s1[k]   += xx[k];
                    a_s2[k]   += xx[k] * xx[k];
                    a_br      += (xx[k] - 2.0f * mm[k]) * xx[k] * iv;
                }
            }
        }

        // ---- stage next tile's x (safe: all passed this iter's sync) ----
        if (nxt < NTILES) {
            float* sb = sxx + (p ^ 1) * TILEF;
            sb[0*DD + 4*(gA ^ 0) + kA] = xn0.x;
            sb[1*DD + 4*(gA ^ 0) + kA] = xn0.y;
            sb[2*DD + 4*(gA ^ 1) + kA] = xn0.z;
            sb[3*DD + 4*(gA ^ 1) + kA] = xn0.w;
            sb[4*DD + 4*(gA ^ 2) + kA] = xn1.x;
            sb[5*DD + 4*(gA ^ 2) + kA] = xn1.y;
            sb[6*DD + 4*(gA ^ 3) + kA] = xn1.z;
            sb[7*DD + 4*(gA ^ 3) + kA] = xn1.w;
        }
        p ^= 1;
    }
    __syncthreads();

    // ---- cross-sub combine via SMEM -> per-d float4, transposed write ----
    #pragma unroll
    for (int k = 0; k < 4; k++) {
        int base = (sub * 128 + dg) * 16 + k * 4;
        sxx[base + 0] = a_sinv[k];
        sxx[base + 1] = a_smui[k];
        sxx[base + 2] = a_s1[k];
        sxx[base + 3] = a_s2[k];
    }
    __syncthreads();
    {
        const int d   = tid;
        const int dg2 = d >> 2, kk = d & 3;
        float4 acc = make_float4(0.f, 0.f, 0.f, 0.f);
        #pragma unroll
        for (int sb = 0; sb < 4; sb++) {
            int base = (sb * 128 + dg2) * 16 + kk * 4;
            acc.x += sxx[base + 0];
            acc.y += sxx[base + 1];
            acc.z += sxx[base + 2];
            acc.w += sxx[base + 3];
        }
        g_part4[(size_t)d * NBP + blk] = acc;   // one store/thread: negligible
    }
    __syncthreads();
    sxx[tid] = a_br;
    __syncthreads();
    #pragma unroll
    for (int off = 256; off > 0; off >>= 1) {
        if (tid < off) sxx[tid] += sxx[tid + off];
        __syncthreads();
    }
    if (tid == 0) g_br[blk] = sxx[0];
}

// ---------------------------------------------------------------------------
// Pass 2: 32 blocks x 512 thr = 512 warps; warp <-> d, lane <-> blk.
// Coalesced float4 reads, shfl butterfly, per-d double term.
// ---------------------------------------------------------------------------
__global__ void club_pass2()
{
    const int tid  = threadIdx.x;
    const int w    = tid >> 5;
    const int lane = tid & 31;
    const int d    = blockIdx.x * 16 + w;

    float4 acc = make_float4(0.f, 0.f, 0.f, 0.f);
    #pragma unroll
    for (int k = 0; k < NBP / 32; k++) {
        float4 v = g_part4[(size_t)d * NBP + k * 32 + lane];
        acc.x += v.x; acc.y += v.y; acc.z += v.z; acc.w += v.w;
    }
    #pragma unroll
    for (int off = 16; off > 0; off >>= 1) {
        acc.x += __shfl_xor_sync(0xFFFFFFFFu, acc.x, off);
        acc.y += __shfl_xor_sync(0xFFFFFFFFu, acc.y, off);
        acc.z += __shfl_xor_sync(0xFFFFFFFFu, acc.z, off);
        acc.w += __shfl_xor_sync(0xFFFFFFFFu, acc.w, off);
    }
    if (lane == 0) {
        double m1 = (double)acc.z / (double)NTOK;
        double m2 = (double)acc.w / (double)NTOK;
        g_cd[d] = -(m2 * (double)acc.x) + 2.0 * m1 * (double)acc.y;
    }
}

// ---------------------------------------------------------------------------
// Pass 3: final deterministic double tree-sum -> scalar.
// ---------------------------------------------------------------------------
__global__ void club_pass3(float* __restrict__ out)
{
    __shared__ double sd[512];
    const int t = threadIdx.x;
    double v = g_cd[t];
    if (t < NBLK) v += (double)g_br[t];
    sd[t] = v;
    __syncthreads();
    #pragma unroll
    for (int off = 256; off > 0; off >>= 1) {
        if (t < off) sd[t] += sd[t + off];
        __syncthreads();
    }
    if (t == 0) out[0] = (float)(-0.5 / (double)NTOK * sd[0]);
}

// ---------------------------------------------------------------------------
extern "C" void kernel_launch(void* const* d_in, const int* in_sizes, int n_in,
                              void* d_out, int out_size)
{
    (void)in_sizes; (void)n_in; (void)out_size;
    const float* x  = (const float*)d_in[0];
    const float* mu = (const float*)d_in[1];
    const float* lv = (const float*)d_in[2];
    float* out = (float*)d_out;

    const int smem = 6 * TILEF * (int)sizeof(float);   // 96 KB dynamic
    cudaFuncSetAttribute(club_pass1, cudaFuncAttributeMaxDynamicSharedMemorySize, smem);

    club_pass1<<<NBLK, TPB, smem>>>(x, mu, lv);
    club_pass2<<<32, TPB>>>();
    club_pass3<<<1, 512>>>(out);
}

// round 12
// speedup vs baseline: 1.2297x; 1.1243x over previous
#include <cuda_runtime.h>
#include <cstddef>

#define DD      512
#define HWV     1024
#define NTOK    16384
#define NBLK    296            // 148 SMs x 2 CTAs -> one wave
#define NBP     320            // padded block rows for pass2 (rows >=296 stay 0)
#define TPB     512
#define TOKTILE 8
#define NTILES  2048           // NTOK / TOKTILE
#define TILEF   (TOKTILE * DD) // floats per smem buffer (4096 = 16KB)

// scratch (device globals zero-initialized; no allocation allowed)
// TRANSPOSED layout [d * NBP + blk] -> pass2 warp reads are coalesced.
__device__ float4 g_part4[DD * NBP];
__device__ float  g_br[NBLK];
__device__ double g_cd[DD];

// ---------------------------------------------------------------------------
// Pass 1 (R6 mainloop, best measured): double-buffered smem x-transpose,
// one sync per tile, pipeline order [mu/lv LDG][next-x LDG][compute][STS][sync].
// Thread t -> dg = t&127 (d = 4dg..4dg+3), sub = t>>7 (2-token subset).
// ---------------------------------------------------------------------------
__global__ __launch_bounds__(TPB, 2)
void club_pass1(const float* __restrict__ x,
                const float* __restrict__ mu,
                const float* __restrict__ lv)
{
    __shared__ float sx[2 * TILEF];        // 32 KB
    const int tid = threadIdx.x;
    const int blk = blockIdx.x;
    const int dg  = tid & 127;
    const int sub = tid >> 7;

    const int gA = tid >> 2;               // d-group for STS (d = tid)
    const int kA = tid & 3;

    float a_sinv[4] = {0,0,0,0};
    float a_smui[4] = {0,0,0,0};
    float a_s1[4]   = {0,0,0,0};
    float a_s2[4]   = {0,0,0,0};
    float a_br = 0.f;

    // ---- prologue: stage tile 'blk' into buffer 0 ----
    {
        const float* xr = x + (size_t)(blk >> 7) * DD * HWV
                            + (size_t)tid * HWV + (blk & 127) * TOKTILE;
        const float4 xa0 = *reinterpret_cast<const float4*>(xr);
        const float4 xa1 = *reinterpret_cast<const float4*>(xr + 4);
        sx[0*DD + 4*(gA ^ 0) + kA] = xa0.x;
        sx[1*DD + 4*(gA ^ 0) + kA] = xa0.y;
        sx[2*DD + 4*(gA ^ 1) + kA] = xa0.z;
        sx[3*DD + 4*(gA ^ 1) + kA] = xa0.w;
        sx[4*DD + 4*(gA ^ 2) + kA] = xa1.x;
        sx[5*DD + 4*(gA ^ 2) + kA] = xa1.y;
        sx[6*DD + 4*(gA ^ 3) + kA] = xa1.z;
        sx[7*DD + 4*(gA ^ 3) + kA] = xa1.w;
    }
    __syncthreads();

    int p = 0;
    for (int t = blk; t < NTILES; t += NBLK) {
        const int nxt = t + NBLK;
        const int t0  = t * TOKTILE;

        // ---- issue mu/lv loads (consumed first in compute) ----
        const float* mup = mu + (size_t)(t0 + sub * 2) * DD + 4 * dg;
        const float* lvp = lv + (size_t)(t0 + sub * 2) * DD + 4 * dg;
        const float4 m0 = *reinterpret_cast<const float4*>(mup);
        const float4 m1 = *reinterpret_cast<const float4*>(mup + DD);
        const float4 l0 = *reinterpret_cast<const float4*>(lvp);
        const float4 l1 = *reinterpret_cast<const float4*>(lvp + DD);

        // ---- issue next-tile x loads (latency hidden under compute) ----
        float4 xn0, xn1;
        if (nxt < NTILES) {
            const float* xr = x + (size_t)(nxt >> 7) * DD * HWV
                                + (size_t)tid * HWV + (nxt & 127) * TOKTILE;
            xn0 = *reinterpret_cast<const float4*>(xr);
            xn1 = *reinterpret_cast<const float4*>(xr + 4);
        }

        // ---- compute on current buffer ----
        {
            const float* cb = sx + p * TILEF;
            #pragma unroll
            for (int j = 0; j < 2; j++) {
                const int ts = sub * 2 + j;
                const float4 xv = *reinterpret_cast<const float4*>(
                    &cb[ts * DD + 4 * (dg ^ ((ts >> 1) & 7))]);
                const float4 mm4 = (j == 0) ? m0 : m1;
                const float4 ll4 = (j == 0) ? l0 : l1;
                float mm[4] = {mm4.x, mm4.y, mm4.z, mm4.w};
                float ll[4] = {ll4.x, ll4.y, ll4.z, ll4.w};
                float xx[4] = {xv.x, xv.y, xv.z, xv.w};
                #pragma unroll
                for (int k = 0; k < 4; k++) {
                    float iv = __expf(-ll[k]);
                    a_sinv[k] += iv;
                    a_smui[k] += mm[k] * iv;
                    a_s1[k]   += xx[k];
                    a_s2[k]   += xx[k] * xx[k];
                    a_br      += (xx[k] - 2.0f * mm[k]) * xx[k] * iv;
                }
            }
        }

        // ---- stage next tile into the other buffer ----
        if (nxt < NTILES) {
            float* sb = sx + (p ^ 1) * TILEF;
            sb[0*DD + 4*(gA ^ 0) + kA] = xn0.x;
            sb[1*DD + 4*(gA ^ 0) + kA] = xn0.y;
            sb[2*DD + 4*(gA ^ 1) + kA] = xn0.z;
            sb[3*DD + 4*(gA ^ 1) + kA] = xn0.w;
            sb[4*DD + 4*(gA ^ 2) + kA] = xn1.x;
            sb[5*DD + 4*(gA ^ 2) + kA] = xn1.y;
            sb[6*DD + 4*(gA ^ 3) + kA] = xn1.z;
            sb[7*DD + 4*(gA ^ 3) + kA] = xn1.w;
        }
        __syncthreads();
        p ^= 1;
    }

    // ---- cross-sub combine via SMEM, then transposed global write ----
    #pragma unroll
    for (int k = 0; k < 4; k++) {
        int base = (sub * 128 + dg) * 16 + k * 4;
        sx[base + 0] = a_sinv[k];
        sx[base + 1] = a_smui[k];
        sx[base + 2] = a_s1[k];
        sx[base + 3] = a_s2[k];
    }
    __syncthreads();
    {
        const int d   = tid;
        const int dg2 = d >> 2, kk = d & 3;
        float4 acc = make_float4(0.f, 0.f, 0.f, 0.f);
        #pragma unroll
        for (int sb = 0; sb < 4; sb++) {
            int base = (sb * 128 + dg2) * 16 + kk * 4;
            acc.x += sx[base + 0];
            acc.y += sx[base + 1];
            acc.z += sx[base + 2];
            acc.w += sx[base + 3];
        }
        // one strided STG.128 per thread, once per kernel -> negligible
        g_part4[(size_t)d * NBP + blk] = acc;
    }
    __syncthreads();
    sx[tid] = a_br;
    __syncthreads();
    #pragma unroll
    for (int off = 256; off > 0; off >>= 1) {
        if (tid < off) sx[tid] += sx[tid + off];
        __syncthreads();
    }
    if (tid == 0) g_br[blk] = sx[0];
}

// ---------------------------------------------------------------------------
// Pass 2: 32 blocks x 512 thr = 512 warps; warp <-> d, lane <-> blk.
// Fully coalesced float4 reads, shfl butterfly, per-d double term:
//   c[d] = -m2*Sinv + 2*m1*Smuinv.  No threadfence handshake (proven slow).
// ---------------------------------------------------------------------------
__global__ void club_pass2()
{
    const int tid  = threadIdx.x;
    const int w    = tid >> 5;
    const int lane = tid & 31;
    const int d    = blockIdx.x * 16 + w;

    float4 acc = make_float4(0.f, 0.f, 0.f, 0.f);
    #pragma unroll
    for (int k = 0; k < NBP / 32; k++) {
        float4 v = g_part4[(size_t)d * NBP + k * 32 + lane];   // coalesced
        acc.x += v.x; acc.y += v.y; acc.z += v.z; acc.w += v.w;
    }
    #pragma unroll
    for (int off = 16; off > 0; off >>= 1) {
        acc.x += __shfl_xor_sync(0xFFFFFFFFu, acc.x, off);
        acc.y += __shfl_xor_sync(0xFFFFFFFFu, acc.y, off);
        acc.z += __shfl_xor_sync(0xFFFFFFFFu, acc.z, off);
        acc.w += __shfl_xor_sync(0xFFFFFFFFu, acc.w, off);
    }
    if (lane == 0) {
        double m1 = (double)acc.z / (double)NTOK;
        double m2 = (double)acc.w / (double)NTOK;
        g_cd[d] = -(m2 * (double)acc.x) + 2.0 * m1 * (double)acc.y;
    }
}

// ---------------------------------------------------------------------------
// Pass 3: final deterministic double tree-sum -> scalar.
// ---------------------------------------------------------------------------
__global__ void club_pass3(float* __restrict__ out)
{
    __shared__ double sd[512];
    const int t = threadIdx.x;
    double v = g_cd[t];
    if (t < NBLK) v += (double)g_br[t];
    sd[t] = v;
    __syncthreads();
    #pragma unroll
    for (int off = 256; off > 0; off >>= 1) {
        if (t < off) sd[t] += sd[t + off];
        __syncthreads();
    }
    if (t == 0) out[0] = (float)(-0.5 / (double)NTOK * sd[0]);
}

// ---------------------------------------------------------------------------
extern "C" void kernel_launch(void* const* d_in, const int* in_sizes, int n_in,
                              void* d_out, int out_size)
{
    (void)in_sizes; (void)n_in; (void)out_size;
    const float* x  = (const float*)d_in[0];
    const float* mu = (const float*)d_in[1];
    const float* lv = (const float*)d_in[2];
    float* out = (float*)d_out;

    club_pass1<<<NBLK, TPB>>>(x, mu, lv);
    club_pass2<<<32, TPB>>>();
    club_pass3<<<1, 512>>>(out);
}